// round 2
// baseline (speedup 1.0000x reference)
#include <cuda_runtime.h>
#include <math.h>

// Problem dims
constexpr int Bn  = 64;
constexpr int Cn  = 512;
constexpr int Sn  = 512;
constexpr int En  = 257;   // rfft length
constexpr int LKn = 128;
constexpr int HKn = 129;
constexpr int Rn  = Bn * Cn;  // 32768 rows (b,c) flattened

// ---------------- scratch (device globals; no allocations allowed) ----------
__device__ float g_Wr[Sn * En];   // forward DFT basis  [s][e]
__device__ float g_Wi[Sn * En];
__device__ float g_Vr[En * Sn];   // inverse basis      [e][s]
__device__ float g_Vi[En * Sn];
__device__ float g_Fr[Rn * En];   // rfft(x)
__device__ float g_Fi[Rn * En];
__device__ float g_Lr[Rn * En];   // low  = crelu(F[:, :128] @ l1 + lb1)
__device__ float g_Li[Rn * En];
__device__ float g_Hr[Rn * En];   // high = crelu(F[:, 128:] @ h1 + hb1)
__device__ float g_Hi[Rn * En];
__device__ float g_S1r[Bn * Cn * Cn];  // scores1 -> becomes P (softmax sum)
__device__ float g_S1i[Bn * Cn * Cn];
__device__ float g_S2r[Bn * Cn * Cn];  // scores2
__device__ float g_S2i[Bn * Cn * Cn];
__device__ float g_Or[Rn * En];   // attention output (pre-irfft)
__device__ float g_Oi[Rn * En];

// ---------------- twiddle init ----------------------------------------------
__global__ void k_twiddle() {
    int idx = blockIdx.x * blockDim.x + threadIdx.x;
    if (idx >= Sn * En) return;
    const float sc0 = 0.044194173824159216f;  // 1/sqrt(512)
    {   // forward: W[s][e] = exp(-2*pi*i*s*e/S)/sqrt(S)
        int s = idx / En, e = idx - s * En;
        int t = (s * e) & (Sn - 1);           // exact mod-512 reduction
        float sv, cv;
        sincospif(2.0f * (float)t / (float)Sn, &sv, &cv);
        g_Wr[idx] = cv * sc0;
        g_Wi[idx] = -sv * sc0;
    }
    {   // inverse (Hermitian folded): out[s] = sum_e Or*Vr + Oi*Vi
        int e = idx / Sn, s = idx - e * Sn;
        int t = (s * e) & (Sn - 1);
        float sv, cv;
        sincospif(2.0f * (float)t / (float)Sn, &sv, &cv);
        float ce = (e == 0 || e == En - 1) ? 1.0f : 2.0f;
        g_Vr[idx] = cv * ce * sc0;
        g_Vi[idx] = -sv * ce * sc0;
    }
}

// ---------------- rfft GEMM: (Fr,Fi) = x(32768x512) @ (Wr,Wi)(512x257) ------
__global__ void __launch_bounds__(256)
k_rfft(const float* __restrict__ x,
       const float* __restrict__ Wr, const float* __restrict__ Wi,
       float* __restrict__ Fr, float* __restrict__ Fi) {
    __shared__ __align__(16) float As[16][68];
    __shared__ __align__(16) float B1s[16][68];
    __shared__ __align__(16) float B2s[16][68];
    const int tid = threadIdx.x;
    const int tx = tid & 15, ty = tid >> 4;
    const int m0 = blockIdx.y * 64, n0 = blockIdx.x * 64;
    const int nl = tid & 63, kq = tid >> 6;
    float c1[4][4] = {}, c2[4][4] = {};

    for (int k0 = 0; k0 < Sn; k0 += 16) {
#pragma unroll
        for (int i = 0; i < 4; i++) {
            int m = ty + i * 16;
            As[tx][m] = x[(long)(m0 + m) * Sn + k0 + tx];
        }
#pragma unroll
        for (int i = 0; i < 4; i++) {
            int k = kq + i * 4;
            int gn = n0 + nl;
            float b1 = 0.f, b2 = 0.f;
            if (gn < En) { long o = (long)(k0 + k) * En + gn; b1 = Wr[o]; b2 = Wi[o]; }
            B1s[k][nl] = b1; B2s[k][nl] = b2;
        }
        __syncthreads();
#pragma unroll
        for (int k = 0; k < 16; k++) {
            float4 a  = *(const float4*)&As[k][ty * 4];
            float4 b1 = *(const float4*)&B1s[k][tx * 4];
            float4 b2 = *(const float4*)&B2s[k][tx * 4];
            float av[4]  = {a.x, a.y, a.z, a.w};
            float b1v[4] = {b1.x, b1.y, b1.z, b1.w};
            float b2v[4] = {b2.x, b2.y, b2.z, b2.w};
#pragma unroll
            for (int i = 0; i < 4; i++)
#pragma unroll
                for (int j = 0; j < 4; j++) {
                    c1[i][j] = fmaf(av[i], b1v[j], c1[i][j]);
                    c2[i][j] = fmaf(av[i], b2v[j], c2[i][j]);
                }
        }
        __syncthreads();
    }
#pragma unroll
    for (int i = 0; i < 4; i++) {
        int gm = m0 + ty * 4 + i;
#pragma unroll
        for (int j = 0; j < 4; j++) {
            int gn = n0 + tx * 4 + j;
            if (gn < En) {
                long o = (long)gm * En + gn;
                Fr[o] = c1[i][j];
                Fi[o] = c2[i][j];
            }
        }
    }
}

// ---------------- generic complex NN GEMM (+bias +relu, batched) ------------
__global__ void __launch_bounds__(256)
k_cgemm_nn(const float* __restrict__ Ar, const float* __restrict__ Ai, int lda, long aStr,
           const float* __restrict__ Br, const float* __restrict__ Bi, int ldb, long bStr,
           float* __restrict__ Cr, float* __restrict__ Ci, int ldc, long cStr,
           int N, int K,
           const float* __restrict__ biasR, const float* __restrict__ biasI, int doRelu) {
    const long bz = blockIdx.z;
    Ar += bz * aStr; Ai += bz * aStr;
    Br += bz * bStr; Bi += bz * bStr;
    Cr += bz * cStr; Ci += bz * cStr;

    __shared__ __align__(16) float Asr[16][68], Asi[16][68];
    __shared__ __align__(16) float Bsr[16][68], Bsi[16][68];
    const int tid = threadIdx.x;
    const int tx = tid & 15, ty = tid >> 4;
    const int m0 = blockIdx.y * 64, n0 = blockIdx.x * 64;
    const int nl = tid & 63, kq = tid >> 6;
    float cr[4][4] = {}, cim[4][4] = {};

    for (int k0 = 0; k0 < K; k0 += 16) {
#pragma unroll
        for (int i = 0; i < 4; i++) {
            int m = ty + i * 16;
            int gk = k0 + tx;
            float ar = 0.f, ai = 0.f;
            if (gk < K) { long o = (long)(m0 + m) * lda + gk; ar = Ar[o]; ai = Ai[o]; }
            Asr[tx][m] = ar; Asi[tx][m] = ai;
        }
#pragma unroll
        for (int i = 0; i < 4; i++) {
            int k = kq + i * 4;
            int gk = k0 + k, gn = n0 + nl;
            float br = 0.f, bi = 0.f;
            if (gk < K && gn < N) { long o = (long)gk * ldb + gn; br = Br[o]; bi = Bi[o]; }
            Bsr[k][nl] = br; Bsi[k][nl] = bi;
        }
        __syncthreads();
#pragma unroll
        for (int k = 0; k < 16; k++) {
            float4 a_r = *(const float4*)&Asr[k][ty * 4];
            float4 a_i = *(const float4*)&Asi[k][ty * 4];
            float4 b_r = *(const float4*)&Bsr[k][tx * 4];
            float4 b_i = *(const float4*)&Bsi[k][tx * 4];
            float arv[4] = {a_r.x, a_r.y, a_r.z, a_r.w};
            float aiv[4] = {a_i.x, a_i.y, a_i.z, a_i.w};
            float brv[4] = {b_r.x, b_r.y, b_r.z, b_r.w};
            float biv[4] = {b_i.x, b_i.y, b_i.z, b_i.w};
#pragma unroll
            for (int i = 0; i < 4; i++)
#pragma unroll
                for (int j = 0; j < 4; j++) {
                    cr[i][j]  = fmaf(arv[i],  brv[j], cr[i][j]);
                    cr[i][j]  = fmaf(-aiv[i], biv[j], cr[i][j]);
                    cim[i][j] = fmaf(arv[i],  biv[j], cim[i][j]);
                    cim[i][j] = fmaf(aiv[i],  brv[j], cim[i][j]);
                }
        }
        __syncthreads();
    }
#pragma unroll
    for (int i = 0; i < 4; i++) {
        int gm = m0 + ty * 4 + i;
#pragma unroll
        for (int j = 0; j < 4; j++) {
            int gn = n0 + tx * 4 + j;
            if (gn < N) {
                float vr = cr[i][j], vi = cim[i][j];
                if (biasR) { vr += biasR[gn]; vi += biasI[gn]; }
                if (doRelu) { vr = fmaxf(vr, 0.f); vi = fmaxf(vi, 0.f); }
                long o = (long)gm * ldc + gn;
                Cr[o] = vr; Ci[o] = vi;
            }
        }
    }
}

// ---------------- complex NT GEMM (scores), batched over blockIdx.z ---------
__global__ void __launch_bounds__(256)
k_cgemm_nt(const float* __restrict__ Ar, const float* __restrict__ Ai,
           const float* __restrict__ Br, const float* __restrict__ Bi,
           float* __restrict__ Cr, float* __restrict__ Ci, float scale) {
    const long aoff = (long)blockIdx.z * Cn * En;
    const long coff = (long)blockIdx.z * Cn * Cn;
    Ar += aoff; Ai += aoff; Br += aoff; Bi += aoff;
    Cr += coff; Ci += coff;

    __shared__ __align__(16) float Asr[16][68], Asi[16][68];
    __shared__ __align__(16) float Bsr[16][68], Bsi[16][68];
    const int tid = threadIdx.x;
    const int tx = tid & 15, ty = tid >> 4;
    const int m0 = blockIdx.y * 64, n0 = blockIdx.x * 64;
    float cr[4][4] = {}, cim[4][4] = {};

    for (int k0 = 0; k0 < En; k0 += 16) {
#pragma unroll
        for (int i = 0; i < 4; i++) {
            int m = ty + i * 16;
            int gk = k0 + tx;
            float ar = 0.f, ai = 0.f;
            if (gk < En) { long o = (long)(m0 + m) * En + gk; ar = Ar[o]; ai = Ai[o]; }
            Asr[tx][m] = ar; Asi[tx][m] = ai;
        }
#pragma unroll
        for (int i = 0; i < 4; i++) {
            int n = ty + i * 16;
            int gk = k0 + tx;
            float br = 0.f, bi = 0.f;
            if (gk < En) { long o = (long)(n0 + n) * En + gk; br = Br[o]; bi = Bi[o]; }
            Bsr[tx][n] = br; Bsi[tx][n] = bi;
        }
        __syncthreads();
#pragma unroll
        for (int k = 0; k < 16; k++) {
            float4 a_r = *(const float4*)&Asr[k][ty * 4];
            float4 a_i = *(const float4*)&Asi[k][ty * 4];
            float4 b_r = *(const float4*)&Bsr[k][tx * 4];
            float4 b_i = *(const float4*)&Bsi[k][tx * 4];
            float arv[4] = {a_r.x, a_r.y, a_r.z, a_r.w};
            float aiv[4] = {a_i.x, a_i.y, a_i.z, a_i.w};
            float brv[4] = {b_r.x, b_r.y, b_r.z, b_r.w};
            float biv[4] = {b_i.x, b_i.y, b_i.z, b_i.w};
#pragma unroll
            for (int i = 0; i < 4; i++)
#pragma unroll
                for (int j = 0; j < 4; j++) {
                    cr[i][j]  = fmaf(arv[i],  brv[j], cr[i][j]);
                    cr[i][j]  = fmaf(-aiv[i], biv[j], cr[i][j]);
                    cim[i][j] = fmaf(arv[i],  biv[j], cim[i][j]);
                    cim[i][j] = fmaf(aiv[i],  brv[j], cim[i][j]);
                }
        }
        __syncthreads();
    }
#pragma unroll
    for (int i = 0; i < 4; i++) {
        int gm = m0 + ty * 4 + i;
#pragma unroll
        for (int j = 0; j < 4; j++) {
            int gn = n0 + tx * 4 + j;
            long o = (long)gm * Cn + gn;
            Cr[o] = scale * cr[i][j];
            Ci[o] = scale * cim[i][j];
        }
    }
}

// ---------------- softmax combine: P = softmax(S1) + softmax(S2), in place --
__global__ void k_softmax(float* __restrict__ S1r, float* __restrict__ S1i,
                          const float* __restrict__ S2r, const float* __restrict__ S2i) {
    __shared__ float2 sh[256];
    const long base = (long)blockIdx.x * Cn;
    const int t = threadIdx.x;

#pragma unroll
    for (int part = 0; part < 2; part++) {
        float* dst        = part ? S1i : S1r;
        const float* src1 = part ? S1i : S1r;
        const float* src2 = part ? S2i : S2r;
        float v1a = src1[base + t], v1b = src1[base + t + 256];
        float v2a = src2[base + t], v2b = src2[base + t + 256];

        sh[t] = make_float2(fmaxf(v1a, v1b), fmaxf(v2a, v2b));
        __syncthreads();
        for (int s = 128; s > 0; s >>= 1) {
            if (t < s) {
                float2 o = sh[t + s];
                sh[t].x = fmaxf(sh[t].x, o.x);
                sh[t].y = fmaxf(sh[t].y, o.y);
            }
            __syncthreads();
        }
        float m1 = sh[0].x, m2 = sh[0].y;
        __syncthreads();

        float e1a = expf(v1a - m1), e1b = expf(v1b - m1);
        float e2a = expf(v2a - m2), e2b = expf(v2b - m2);
        sh[t] = make_float2(e1a + e1b, e2a + e2b);
        __syncthreads();
        for (int s = 128; s > 0; s >>= 1) {
            if (t < s) {
                float2 o = sh[t + s];
                sh[t].x += o.x;
                sh[t].y += o.y;
            }
            __syncthreads();
        }
        float r1 = 1.f / sh[0].x, r2 = 1.f / sh[0].y;
        __syncthreads();

        dst[base + t]       = e1a * r1 + e2a * r2;
        dst[base + t + 256] = e1b * r1 + e2b * r2;
    }
}

// ---------------- irfft GEMM: out = Or@Vr + Oi@Vi ---------------------------
__global__ void __launch_bounds__(256)
k_irfft(const float* __restrict__ Ar, const float* __restrict__ Ai,
        const float* __restrict__ B1, const float* __restrict__ B2,
        float* __restrict__ out) {
    __shared__ __align__(16) float Asr[16][68], Asi[16][68];
    __shared__ __align__(16) float B1s[16][68], B2s[16][68];
    const int tid = threadIdx.x;
    const int tx = tid & 15, ty = tid >> 4;
    const int m0 = blockIdx.y * 64, n0 = blockIdx.x * 64;
    const int nl = tid & 63, kq = tid >> 6;
    float c[4][4] = {};

    for (int k0 = 0; k0 < En; k0 += 16) {
#pragma unroll
        for (int i = 0; i < 4; i++) {
            int m = ty + i * 16;
            int gk = k0 + tx;
            float ar = 0.f, ai = 0.f;
            if (gk < En) { long o = (long)(m0 + m) * En + gk; ar = Ar[o]; ai = Ai[o]; }
            Asr[tx][m] = ar; Asi[tx][m] = ai;
        }
#pragma unroll
        for (int i = 0; i < 4; i++) {
            int k = kq + i * 4;
            int gk = k0 + k, gn = n0 + nl;
            float b1 = 0.f, b2 = 0.f;
            if (gk < En) { long o = (long)gk * Sn + gn; b1 = B1[o]; b2 = B2[o]; }
            B1s[k][nl] = b1; B2s[k][nl] = b2;
        }
        __syncthreads();
#pragma unroll
        for (int k = 0; k < 16; k++) {
            float4 a_r = *(const float4*)&Asr[k][ty * 4];
            float4 a_i = *(const float4*)&Asi[k][ty * 4];
            float4 b_1 = *(const float4*)&B1s[k][tx * 4];
            float4 b_2 = *(const float4*)&B2s[k][tx * 4];
            float arv[4] = {a_r.x, a_r.y, a_r.z, a_r.w};
            float aiv[4] = {a_i.x, a_i.y, a_i.z, a_i.w};
            float b1v[4] = {b_1.x, b_1.y, b_1.z, b_1.w};
            float b2v[4] = {b_2.x, b_2.y, b_2.z, b_2.w};
#pragma unroll
            for (int i = 0; i < 4; i++)
#pragma unroll
                for (int j = 0; j < 4; j++) {
                    c[i][j] = fmaf(arv[i], b1v[j], c[i][j]);
                    c[i][j] = fmaf(aiv[i], b2v[j], c[i][j]);
                }
        }
        __syncthreads();
    }
#pragma unroll
    for (int i = 0; i < 4; i++) {
        int gm = m0 + ty * 4 + i;
#pragma unroll
        for (int j = 0; j < 4; j++) {
            int gn = n0 + tx * 4 + j;
            out[(long)gm * Sn + gn] = c[i][j];
        }
    }
}

// ---------------- launch ----------------------------------------------------
extern "C" void kernel_launch(void* const* d_in, const int* in_sizes, int n_in,
                              void* d_out, int out_size) {
    const float* x    = (const float*)d_in[0];
    const float* l1r  = (const float*)d_in[1];
    const float* l1i  = (const float*)d_in[2];
    const float* h1r  = (const float*)d_in[3];
    const float* h1i  = (const float*)d_in[4];
    const float* lb1r = (const float*)d_in[5];
    const float* lb1i = (const float*)d_in[6];
    const float* hb1r = (const float*)d_in[7];
    const float* hb1i = (const float*)d_in[8];
    float* out = (float*)d_out;

    float *Wr, *Wi, *Vr, *Vi, *Fr, *Fi, *Lr, *Li, *Hr, *Hi;
    float *S1r, *S1i, *S2r, *S2i, *Or, *Oi;
    cudaGetSymbolAddress((void**)&Wr, g_Wr);
    cudaGetSymbolAddress((void**)&Wi, g_Wi);
    cudaGetSymbolAddress((void**)&Vr, g_Vr);
    cudaGetSymbolAddress((void**)&Vi, g_Vi);
    cudaGetSymbolAddress((void**)&Fr, g_Fr);
    cudaGetSymbolAddress((void**)&Fi, g_Fi);
    cudaGetSymbolAddress((void**)&Lr, g_Lr);
    cudaGetSymbolAddress((void**)&Li, g_Li);
    cudaGetSymbolAddress((void**)&Hr, g_Hr);
    cudaGetSymbolAddress((void**)&Hi, g_Hi);
    cudaGetSymbolAddress((void**)&S1r, g_S1r);
    cudaGetSymbolAddress((void**)&S1i, g_S1i);
    cudaGetSymbolAddress((void**)&S2r, g_S2r);
    cudaGetSymbolAddress((void**)&S2i, g_S2i);
    cudaGetSymbolAddress((void**)&Or, g_Or);
    cudaGetSymbolAddress((void**)&Oi, g_Oi);

    const float scale = 1.0f / sqrtf((float)En);

    // 1. DFT bases
    k_twiddle<<<(Sn * En + 255) / 256, 256>>>();

    // 2. rfft
    k_rfft<<<dim3(5, Rn / 64), 256>>>(x, Wr, Wi, Fr, Fi);

    // 3. low / high band complex linear + bias + crelu
    k_cgemm_nn<<<dim3(5, Rn / 64), 256>>>(Fr, Fi, En, 0, l1r, l1i, En, 0,
                                          Lr, Li, En, 0, En, LKn, lb1r, lb1i, 1);
    k_cgemm_nn<<<dim3(5, Rn / 64), 256>>>(Fr + LKn, Fi + LKn, En, 0, h1r, h1i, En, 0,
                                          Hr, Hi, En, 0, En, HKn, hb1r, hb1i, 1);

    // 4. scores: S1 = scale * L @ L^T, S2 = scale * L @ H^T (batched over B)
    k_cgemm_nt<<<dim3(8, 8, Bn), 256>>>(Lr, Li, Lr, Li, S1r, S1i, scale);
    k_cgemm_nt<<<dim3(8, 8, Bn), 256>>>(Lr, Li, Hr, Hi, S2r, S2i, scale);

    // 5. P = softmax(S1) + softmax(S2) (per real/imag plane, in place -> S1)
    k_softmax<<<Rn, 256>>>(S1r, S1i, S2r, S2i);

    // 6. O = P @ L (complex, batched)
    k_cgemm_nn<<<dim3(5, 8, Bn), 256>>>(S1r, S1i, Cn, (long)Cn * Cn,
                                        Lr, Li, En, (long)Cn * En,
                                        Or, Oi, En, (long)Cn * En,
                                        En, Cn, nullptr, nullptr, 0);

    // 7. irfft -> output
    k_irfft<<<dim3(8, Rn / 64), 256>>>(Or, Oi, Vr, Vi, out);
}

// round 5
// speedup vs baseline: 1.1886x; 1.1886x over previous
#include <cuda_runtime.h>
#include <math.h>
#include <stdint.h>

constexpr int Sn=512, En=257, E2=288, N2=576, Bn=64, Cnn=512, Rn=32768;

// ---------------- device scratch -------------------------------------------
__device__ float g_W[N2*Sn];              // rfft  B  [576][512]
__device__ float g_Vb[Sn*N2];             // irfft B  [512][576]
__device__ float g_WbL[N2*256];           // low-band  B [576][256]
__device__ float g_WbH[N2*320];           // high-band B [576][320]
__device__ float g_biasL[N2], g_biasH[N2];
__device__ float g_F[(long)Rn*N2];        // [Fr|Fi]
__device__ float g_Lb[(long)Rn*N2];       // [Lr|Li]   (A side, raw fp32)
__device__ float g_LBr[(long)Rn*N2];      // [Lr|-Li]
__device__ float g_LBi[(long)Rn*N2];      // [Li| Lr]
__device__ float g_HBr[(long)Rn*N2];
__device__ float g_HBi[(long)Rn*N2];
__device__ float g_S1[(long)Bn*Cnn*1024]; // [S1r|S1i] -> P (rna) after softmax
__device__ float g_S2[(long)Bn*Cnn*1024];
__device__ float g_Bpv[(long)Bn*N2*1024]; // PV B: rows e:[LrT|-LiT], 288+e:[LiT|LrT]
__device__ float g_O[(long)Rn*N2];        // [Or|Oi] (rna)

// ---------------- helpers ---------------------------------------------------
__device__ __forceinline__ float rnaf(float v){
    uint32_t u; asm("cvt.rna.tf32.f32 %0,%1;":"=r"(u):"f"(v));
    return __uint_as_float(u);
}
__device__ __forceinline__ void splitf(float v, uint32_t& h, uint32_t& l){
    asm("cvt.rna.tf32.f32 %0,%1;":"=r"(h):"f"(v));
    float r = v - __uint_as_float(h);
    asm("cvt.rna.tf32.f32 %0,%1;":"=r"(l):"f"(r));
}
__device__ __forceinline__ void mma8(float* c, const uint32_t* a, const uint32_t* b){
    asm volatile("mma.sync.aligned.m16n8k8.row.col.f32.tf32.tf32.f32 "
        "{%0,%1,%2,%3},{%4,%5,%6,%7},{%8,%9},{%0,%1,%2,%3};"
        : "+f"(c[0]),"+f"(c[1]),"+f"(c[2]),"+f"(c[3])
        : "r"(a[0]),"r"(a[1]),"r"(a[2]),"r"(a[3]),"r"(b[0]),"r"(b[1]));
}
__device__ __forceinline__ uint32_t s2u(const void* p){
    uint32_t a; asm("{ .reg .u64 t; cvta.to.shared.u64 t,%1; cvt.u32.u64 %0,t; }":"=r"(a):"l"(p));
    return a;
}

// ---------------- prep kernels ----------------------------------------------
__global__ void k_W(){
    int i = blockIdx.x*256 + threadIdx.x;
    if (i >= N2*Sn) return;
    int n = i/Sn, s = i - n*Sn;
    int p = n >= E2; int e = n - (p?E2:0);
    float v = 0.f;
    if (e < En) {
        int t = (s*e) & 511; float sv, cv;
        sincospif(2.f*(float)t/512.f, &sv, &cv);
        const float sc = 0.044194173824159216f;
        v = p ? -sv*sc : cv*sc;
    }
    g_W[i] = v;
}
__global__ void k_Vb(){
    int i = blockIdx.x*256 + threadIdx.x;
    if (i >= Sn*N2) return;
    int s = i/N2, k = i - s*N2;
    int p = k >= E2; int e = k - (p?E2:0);
    float v = 0.f;
    if (e < En) {
        int t = (s*e) & 511; float sv, cv;
        sincospif(2.f*(float)t/512.f, &sv, &cv);
        const float sc = 0.044194173824159216f;
        float ce = (e==0 || e==En-1) ? 1.f : 2.f;
        v = p ? -sv*ce*sc : cv*ce*sc;
    }
    g_Vb[i] = v;
}
__global__ void k_WbL(const float* __restrict__ l1r, const float* __restrict__ l1i){
    int i = blockIdx.x*256 + threadIdx.x;
    if (i >= N2*256) return;
    int n = i/256, k = i - n*256;
    int p = n >= E2; int e = n - (p?E2:0);
    float v = 0.f;
    if (e < En) {
        if (k < 128) v = p ? l1i[k*En+e] : l1r[k*En+e];
        else { int kk = k-128; v = p ? l1r[kk*En+e] : -l1i[kk*En+e]; }
    }
    g_WbL[i] = v;
}
__global__ void k_WbH(const float* __restrict__ h1r, const float* __restrict__ h1i){
    int i = blockIdx.x*256 + threadIdx.x;
    if (i >= N2*320) return;
    int n = i/320, k = i - n*320;
    int p = n >= E2; int e = n - (p?E2:0);
    float v = 0.f;
    if (e < En) {
        if (k < 160) { if (k < 129) v = p ? h1i[k*En+e] : h1r[k*En+e]; }
        else { int kk = k-160; if (kk < 129) v = p ? h1r[kk*En+e] : -h1i[kk*En+e]; }
    }
    g_WbH[i] = v;
}
__global__ void k_bias(const float* lr, const float* li, const float* hr, const float* hi){
    int i = blockIdx.x*256 + threadIdx.x;
    if (i >= 2*N2) return;
    int w = i/N2, n = i - w*N2;
    int p = n >= E2; int e = n - (p?E2:0);
    float v = 0.f;
    if (e < En) v = w ? (p ? hi[e] : hr[e]) : (p ? li[e] : lr[e]);
    if (w) g_biasH[n] = v; else g_biasL[n] = v;
}
__global__ void k_softmax(){
    __shared__ float2 sh[256];
    const long base = (long)blockIdx.x*1024;
    const int t = threadIdx.x;
#pragma unroll
    for (int pl = 0; pl < 2; pl++) {
        long b = base + pl*512;
        float v1a = g_S1[b+t], v1b = g_S1[b+t+256];
        float v2a = g_S2[b+t], v2b = g_S2[b+t+256];
        sh[t] = make_float2(fmaxf(v1a,v1b), fmaxf(v2a,v2b));
        __syncthreads();
        for (int s = 128; s > 0; s >>= 1) {
            if (t < s) { float2 o = sh[t+s]; sh[t].x = fmaxf(sh[t].x,o.x); sh[t].y = fmaxf(sh[t].y,o.y); }
            __syncthreads();
        }
        float m1 = sh[0].x, m2 = sh[0].y; __syncthreads();
        float e1a = expf(v1a-m1), e1b = expf(v1b-m1);
        float e2a = expf(v2a-m2), e2b = expf(v2b-m2);
        sh[t] = make_float2(e1a+e1b, e2a+e2b);
        __syncthreads();
        for (int s = 128; s > 0; s >>= 1) {
            if (t < s) { float2 o = sh[t+s]; sh[t].x += o.x; sh[t].y += o.y; }
            __syncthreads();
        }
        float r1 = 1.f/sh[0].x, r2 = 1.f/sh[0].y; __syncthreads();
        g_S1[b+t]     = rnaf(e1a*r1 + e2a*r2);
        g_S1[b+t+256] = rnaf(e1b*r1 + e2b*r2);
    }
}
__global__ void k_bpv(){
    __shared__ float t0[32][33], t1[32][33];
    int e0 = blockIdx.x*32, c0 = blockIdx.y*32, b = blockIdx.z;
    int tx = threadIdx.x, ty = threadIdx.y;
    long inB = (long)b*Cnn*N2, outB = (long)b*N2*1024;
#pragma unroll
    for (int i = 0; i < 4; i++) {
        int c = c0 + ty + i*8;
        t0[ty+i*8][tx] = g_Lb[inB + (long)c*N2 + e0+tx];
        t1[ty+i*8][tx] = g_Lb[inB + (long)c*N2 + E2 + e0+tx];
    }
    __syncthreads();
#pragma unroll
    for (int i = 0; i < 4; i++) {
        int e = e0 + ty + i*8, c = c0 + tx;
        float lr = t0[tx][ty+i*8], li = t1[tx][ty+i*8];
        g_Bpv[outB + (long)e*1024 + c]            = lr;
        g_Bpv[outB + (long)e*1024 + 512 + c]      = -li;
        g_Bpv[outB + (long)(E2+e)*1024 + c]       = li;
        g_Bpv[outB + (long)(E2+e)*1024 + 512 + c] = lr;
    }
}

// ---------------- generic tf32 mma.sync GEMM (NT) ---------------------------
// C[m][n] = scale * sum_k A[m][k] * B[n][k]   (+bias +relu, multi-dest)
struct GP {
    const float *A, *B, *B2;
    float *C, *d1, *d2;
    const float* bias;
    long aB, bB, cB;
    int lda, ldb, ldc, K, K1, gap, N, NB1, relu;
    float scale;
};

__device__ __forceinline__ void do_load(const GP& g, const float* Ab,
        const float* Bb1, const float* Bb2, uint32_t uA, uint32_t uB,
        int tid, int m0, int n0, int st, int kt){
    int k0 = kt << 4;
#pragma unroll
    for (int i = 0; i < 2; i++) {
        int q = tid + i*256;
        int row = q >> 2, kk = (q & 3) << 2;
        int kg = k0 + kk;
        int col = kg < g.K1 ? kg : kg + g.gap;
        const float* src = Ab + (long)(m0+row)*g.lda + col;
        uint32_t dst = uA + (uint32_t)(st*2560 + row*20 + kk)*4;
        asm volatile("cp.async.ca.shared.global [%0],[%1],16;"::"r"(dst),"l"(src));
    }
#pragma unroll
    for (int i = 0; i < 2; i++) {
        int q = tid + i*256;
        int row = q >> 2, kk = (q & 3) << 2;
        int brow = n0 + row;
        int ok = brow < g.N;
        int bc = ok ? brow : 0;
        const float* src = (bc < g.NB1 ? Bb1 + (long)bc*g.ldb
                                       : Bb2 + (long)(bc-g.NB1)*g.ldb) + k0 + kk;
        uint32_t dst = uB + (uint32_t)(st*2560 + row*20 + kk)*4;
        int sz = ok ? 16 : 0;
        asm volatile("cp.async.ca.shared.global [%0],[%1],16,%2;"::"r"(dst),"l"(src),"r"(sz));
    }
}

template<int MODE, int EPI>   // MODE: 3 = split A&B (3 mma), 2 = A tf32-exact, split B (2 mma)
__global__ void __launch_bounds__(256,1) k_mm(const GP g){
    __shared__ float sA[2][128*20];
    __shared__ float sB[2][128*20];
    const int tid = threadIdx.x, lane = tid & 31, wid = tid >> 5;
    const int wm = wid & 1, wn = wid >> 1;
    const int m0 = blockIdx.y*128, n0 = blockIdx.x*128, bz = blockIdx.z;
    const float* Ab  = g.A  + (long)bz*g.aB;
    const float* Bb1 = g.B  + (long)bz*g.bB;
    const float* Bb2 = g.B2 + (long)bz*g.bB;
    const uint32_t uA = s2u(sA), uB = s2u(sB);
    const int KT = g.K >> 4;

    float acc[4][4][4];
#pragma unroll
    for (int a = 0; a < 4; a++)
#pragma unroll
        for (int b = 0; b < 4; b++)
#pragma unroll
            for (int c = 0; c < 4; c++) acc[a][b][c] = 0.f;

    do_load(g, Ab, Bb1, Bb2, uA, uB, tid, m0, n0, 0, 0);
    asm volatile("cp.async.commit_group;");

    for (int kt = 0; kt < KT; kt++) {
        if (kt+1 < KT) do_load(g, Ab, Bb1, Bb2, uA, uB, tid, m0, n0, (kt+1)&1, kt+1);
        asm volatile("cp.async.commit_group;");
        asm volatile("cp.async.wait_group 1;");
        __syncthreads();
        const float* As = sA[kt & 1];
        const float* Bs = sB[kt & 1];
#pragma unroll
        for (int ks = 0; ks < 2; ks++) {
            int kb = ks*8 + (lane & 3);
            uint32_t bh[4][2], bl[4][2];
#pragma unroll
            for (int ni = 0; ni < 4; ni++) {
                int rn = wn*32 + ni*8 + (lane >> 2);
                splitf(Bs[rn*20 + kb],   bh[ni][0], bl[ni][0]);
                splitf(Bs[rn*20 + kb+4], bh[ni][1], bl[ni][1]);
            }
#pragma unroll
            for (int mi = 0; mi < 4; mi++) {
                int r0 = wm*64 + mi*16 + (lane >> 2);
                float a0 = As[r0*20+kb],     a1 = As[(r0+8)*20+kb];
                float a2 = As[r0*20+kb+4],   a3 = As[(r0+8)*20+kb+4];
                if (MODE == 3) {
                    uint32_t ah[4], al[4];
                    splitf(a0, ah[0], al[0]); splitf(a1, ah[1], al[1]);
                    splitf(a2, ah[2], al[2]); splitf(a3, ah[3], al[3]);
#pragma unroll
                    for (int ni = 0; ni < 4; ni++) {
                        mma8(acc[mi][ni], ah, bh[ni]);
                        mma8(acc[mi][ni], ah, bl[ni]);
                        mma8(acc[mi][ni], al, bh[ni]);
                    }
                } else {
                    uint32_t a[4] = {__float_as_uint(a0), __float_as_uint(a1),
                                     __float_as_uint(a2), __float_as_uint(a3)};
#pragma unroll
                    for (int ni = 0; ni < 4; ni++) {
                        mma8(acc[mi][ni], a, bh[ni]);
                        mma8(acc[mi][ni], a, bl[ni]);
                    }
                }
            }
        }
        __syncthreads();
    }

    float* Cb = g.C ? g.C + (long)bz*g.cB : nullptr;
#pragma unroll
    for (int mi = 0; mi < 4; mi++)
#pragma unroll
    for (int ni = 0; ni < 4; ni++)
#pragma unroll
    for (int rg = 0; rg < 4; rg++) {
        int row = m0 + wm*64 + mi*16 + (lane >> 2) + ((rg >= 2) ? 8 : 0);
        int col = n0 + wn*32 + ni*8 + (lane & 3)*2 + (rg & 1);
        if (col < g.N) {
            float v = acc[mi][ni][rg] * g.scale;
            if (g.bias) v += g.bias[col];
            if (g.relu) v = fmaxf(v, 0.f);
            if (EPI == 0) {
                Cb[(long)row*g.ldc + col] = v;
            } else if (EPI == 1) {
                Cb[(long)row*g.ldc + col] = rnaf(v);
            } else {  // band: C=[Lr|Li], d1=[Lr|-Li], d2=[Li|Lr]
                int p = col >= E2; int e = col - (p ? E2 : 0);
                if (Cb) Cb[(long)row*g.ldc + col] = v;
                g.d1[(long)row*N2 + (p ? E2+e : e)] = p ? -v : v;
                g.d2[(long)row*N2 + (p ? e : E2+e)] = v;
            }
        }
    }
}

// ---------------- host ------------------------------------------------------
#define SYM(name) ({ void* _p; cudaGetSymbolAddress(&_p, name); (float*)_p; })

extern "C" void kernel_launch(void* const* d_in, const int* in_sizes, int n_in,
                              void* d_out, int out_size) {
    const float* x    = (const float*)d_in[0];
    const float* l1r  = (const float*)d_in[1];
    const float* l1i  = (const float*)d_in[2];
    const float* h1r  = (const float*)d_in[3];
    const float* h1i  = (const float*)d_in[4];
    const float* lb1r = (const float*)d_in[5];
    const float* lb1i = (const float*)d_in[6];
    const float* hb1r = (const float*)d_in[7];
    const float* hb1i = (const float*)d_in[8];
    float* out = (float*)d_out;

    float* W   = SYM(g_W);   float* Vb  = SYM(g_Vb);
    float* WbL = SYM(g_WbL); float* WbH = SYM(g_WbH);
    float* bL  = SYM(g_biasL); float* bH = SYM(g_biasH);
    float* F   = SYM(g_F);   float* Lb  = SYM(g_Lb);
    float* LBr = SYM(g_LBr); float* LBi = SYM(g_LBi);
    float* HBr = SYM(g_HBr); float* HBi = SYM(g_HBi);
    float* S1  = SYM(g_S1);  float* S2  = SYM(g_S2);
    float* Bpv = SYM(g_Bpv); float* O   = SYM(g_O);

    // prep
    k_W  <<<(N2*Sn+255)/256, 256>>>();
    k_Vb <<<(Sn*N2+255)/256, 256>>>();
    k_WbL<<<(N2*256+255)/256, 256>>>(l1r, l1i);
    k_WbH<<<(N2*320+255)/256, 256>>>(h1r, h1i);
    k_bias<<<(2*N2+255)/256, 256>>>(lb1r, lb1i, hb1r, hb1i);

    GP g{};
    const int BIG = 1 << 30;

    // 1) rfft: F = x @ W^T   M=32768 N=576 K=512
    g = GP{}; g.A = x; g.B = W; g.B2 = W; g.C = F;
    g.lda = 512; g.ldb = 512; g.ldc = N2;
    g.K = 512; g.K1 = 512; g.gap = 0; g.N = N2; g.NB1 = BIG; g.scale = 1.f;
    k_mm<3,0><<<dim3(5,256,1), 256>>>(g);

    // 2) low band: Lb/[LBr,LBi] = crelu(F_low @ wl + lb)   K=256 (segs 128@0,128@288)
    g = GP{}; g.A = F; g.B = WbL; g.B2 = WbL; g.C = Lb; g.d1 = LBr; g.d2 = LBi;
    g.bias = bL; g.relu = 1;
    g.lda = N2; g.ldb = 256; g.ldc = N2;
    g.K = 256; g.K1 = 128; g.gap = 160; g.N = N2; g.NB1 = BIG; g.scale = 1.f;
    k_mm<3,2><<<dim3(5,256,1), 256>>>(g);

    // 3) high band: [HBr,HBi]   K=320 (segs 160@128, 160@416)
    g = GP{}; g.A = F + 128; g.B = WbH; g.B2 = WbH; g.C = nullptr; g.d1 = HBr; g.d2 = HBi;
    g.bias = bH; g.relu = 1;
    g.lda = N2; g.ldb = 320; g.ldc = N2;
    g.K = 320; g.K1 = 160; g.gap = 128; g.N = N2; g.NB1 = BIG; g.scale = 1.f;
    k_mm<3,2><<<dim3(5,256,1), 256>>>(g);

    const float sscale = 1.0f / sqrtf((float)En);

    // 4) scores S1 = scale * L @ [LBr;LBi]^T  per batch: M=512 N=1024 K=576
    g = GP{}; g.A = Lb; g.B = LBr; g.B2 = LBi; g.C = S1;
    g.aB = (long)Cnn*N2; g.bB = (long)Cnn*N2; g.cB = (long)Cnn*1024;
    g.lda = N2; g.ldb = N2; g.ldc = 1024;
    g.K = N2; g.K1 = N2; g.gap = 0; g.N = 1024; g.NB1 = 512; g.scale = sscale;
    k_mm<3,0><<<dim3(8,4,64), 256>>>(g);

    // 5) scores S2 (K-side = high band)
    g.B = HBr; g.B2 = HBi; g.C = S2;
    k_mm<3,0><<<dim3(8,4,64), 256>>>(g);

    // 6) P = softmax(S1)+softmax(S2) (rna, in place into S1); build PV B-matrix
    k_softmax<<<Rn, 256>>>();
    k_bpv<<<dim3(9,16,64), dim3(32,8)>>>();

    // 7) O = P @ Bpv^T  per batch: M=512 N=576 K=1024  (A tf32-exact, split B)
    g = GP{}; g.A = S1; g.B = Bpv; g.B2 = Bpv; g.C = O;
    g.aB = (long)Cnn*1024; g.bB = (long)N2*1024; g.cB = (long)Cnn*N2;
    g.lda = 1024; g.ldb = 1024; g.ldc = N2;
    g.K = 1024; g.K1 = 1024; g.gap = 0; g.N = N2; g.NB1 = BIG; g.scale = 1.f;
    k_mm<2,1><<<dim3(5,4,64), 256>>>(g);

    // 8) irfft: out = O @ Vb^T   M=32768 N=512 K=576
    g = GP{}; g.A = O; g.B = Vb; g.B2 = Vb; g.C = out;
    g.lda = N2; g.ldb = N2; g.ldc = 512;
    g.K = N2; g.K1 = N2; g.gap = 0; g.N = 512; g.NB1 = BIG; g.scale = 1.f;
    k_mm<2,0><<<dim3(4,256,1), 256>>>(g);
}